// round 1
// baseline (speedup 1.0000x reference)
#include <cuda_runtime.h>
#include <math.h>
#include <float.h>

// Problem constants (match reference)
#define NN 100000
#define NE 1600000
#define NF 128
#define NL 7
#define SLOPE 0.02f

#define SCAN_T 1024
#define SCAN_B ((NN + SCAN_T - 1) / SCAN_T)   // 98

// ---------------- device scratch (static, no allocation) ----------------
__device__ int   g_counts[NN];
__device__ int   g_cursor[NN];
__device__ int   g_rowptr[NN + 1];
__device__ int   g_col[NE];
__device__ int   g_blocksum[SCAN_B];
__device__ float g_h0[NN * NF];
__device__ float g_h1[NN * NF];
__device__ float g_agg[NN * NF];
__device__ float g_WlT[NL * NF * NF];   // [l][k][n] = Wl[l][n][k]
__device__ float g_WrT[NL * NF * NF];

// ---------------- CSR build ----------------
__global__ void zero_kernel() {
    int i = blockIdx.x * blockDim.x + threadIdx.x;
    if (i < NN) { g_counts[i] = 0; g_cursor[i] = 0; }
}

__global__ void hist_kernel(const int* __restrict__ dst) {
    int e = blockIdx.x * blockDim.x + threadIdx.x;
    if (e < NE) atomicAdd(&g_counts[dst[e]], 1);
}

__global__ void scan1_kernel() {
    __shared__ int s[SCAN_T];
    int t = threadIdx.x;
    int i = blockIdx.x * SCAN_T + t;
    int v = (i < NN) ? g_counts[i] : 0;
    s[t] = v;
    __syncthreads();
#pragma unroll
    for (int d = 1; d < SCAN_T; d <<= 1) {
        int add = (t >= d) ? s[t - d] : 0;
        __syncthreads();
        s[t] += add;
        __syncthreads();
    }
    if (i < NN) g_rowptr[i] = s[t];           // inclusive scan (temp)
    if (t == SCAN_T - 1) g_blocksum[blockIdx.x] = s[t];
}

__global__ void scan2_kernel() {
    int running = 0;
    for (int b = 0; b < SCAN_B; b++) {
        int v = g_blocksum[b];
        g_blocksum[b] = running;
        running += v;
    }
}

__global__ void scan3_kernel() {
    int t = threadIdx.x;
    int i = blockIdx.x * SCAN_T + t;
    if (i < NN) {
        g_rowptr[i] = g_rowptr[i] - g_counts[i] + g_blocksum[blockIdx.x]; // exclusive
    }
    if (i == 0) g_rowptr[NN] = NE;
}

__global__ void fill_kernel(const int* __restrict__ src, const int* __restrict__ dst) {
    int e = blockIdx.x * blockDim.x + threadIdx.x;
    if (e < NE) {
        int d = dst[e];
        int off = atomicAdd(&g_cursor[d], 1);
        g_col[g_rowptr[d] + off] = src[e];
    }
}

// ---------------- weight transpose: WT[l][k][n] = W[l][n][k] ----------------
__global__ void transpose_kernel(const float* __restrict__ Wl, const float* __restrict__ Wr) {
    int idx = blockIdx.x * blockDim.x + threadIdx.x;
    if (idx >= NL * NF * NF) return;
    int l = idx / (NF * NF);
    int r = idx % (NF * NF);
    int k = r / NF;   // input channel
    int n = r % NF;   // output channel
    g_WlT[idx] = Wl[l * NF * NF + n * NF + k];
    g_WrT[idx] = Wr[l * NF * NF + n * NF + k];
}

// ---------------- max aggregation: warp per node, float4 per lane ----------------
__device__ __forceinline__ float4 fmax4(float4 a, float4 b) {
    a.x = fmaxf(a.x, b.x); a.y = fmaxf(a.y, b.y);
    a.z = fmaxf(a.z, b.z); a.w = fmaxf(a.w, b.w);
    return a;
}

__global__ __launch_bounds__(256) void agg_kernel(const float* __restrict__ h,
                                                  float* __restrict__ agg) {
    int warp = (blockIdx.x * blockDim.x + threadIdx.x) >> 5;
    int lane = threadIdx.x & 31;
    if (warp >= NN) return;
    int beg = g_rowptr[warp];
    int end = g_rowptr[warp + 1];
    const float4* h4 = (const float4*)h;
    float4 m = make_float4(-FLT_MAX, -FLT_MAX, -FLT_MAX, -FLT_MAX);
    int e = beg;
    for (; e + 4 <= end; e += 4) {
        int s0 = g_col[e], s1 = g_col[e + 1], s2 = g_col[e + 2], s3 = g_col[e + 3];
        float4 v0 = h4[s0 * 32 + lane];
        float4 v1 = h4[s1 * 32 + lane];
        float4 v2 = h4[s2 * 32 + lane];
        float4 v3 = h4[s3 * 32 + lane];
        m = fmax4(m, fmax4(fmax4(v0, v1), fmax4(v2, v3)));
    }
    for (; e < end; e++) {
        int s = g_col[e];
        m = fmax4(m, h4[s * 32 + lane]);
    }
    if (beg == end) m = make_float4(0.f, 0.f, 0.f, 0.f);
    ((float4*)agg)[warp * 32 + lane] = m;
}

// ---------------- fused dual GEMM + bias + leaky ----------------
// C[M,128] = A0[M,128] @ B0[128,128](k-major) + A1[M,128] @ B1 + bias, then leaky.
__global__ __launch_bounds__(256) void gemm128_kernel(
    const float* __restrict__ A0, const float* __restrict__ A1,
    const float* __restrict__ B0, const float* __restrict__ B1,
    const float* __restrict__ bias, float* __restrict__ C, int M)
{
    __shared__ float As[16][132];   // padded: 132*4B keeps 16B alignment, breaks conflicts
    __shared__ float Bs[16][128];

    int tid = threadIdx.x;
    int tx = tid & 15;        // 0..15 -> cols tx*8..tx*8+7
    int ty = tid >> 4;        // 0..15 -> rows ty*8..ty*8+7
    int rowBase = blockIdx.x * 128;

    float acc[8][8];
#pragma unroll
    for (int i = 0; i < 8; i++)
#pragma unroll
        for (int j = 0; j < 8; j++) acc[i][j] = 0.f;

#pragma unroll
    for (int half = 0; half < 2; half++) {
        const float4* A4 = (const float4*)(half ? A1 : A0);
        const float4* B4 = (const float4*)(half ? B1 : B0);
        for (int k0 = 0; k0 < 128; k0 += 16) {
            // load A tile (128 rows x 16 k), store k-major into As
#pragma unroll
            for (int i = 0; i < 2; i++) {
                int idx = tid + i * 256;          // 0..511
                int r = idx >> 2;                  // 0..127
                int q = idx & 3;                   // float4 within the 16-k chunk
                int gm = rowBase + r;
                float4 av = make_float4(0.f, 0.f, 0.f, 0.f);
                if (gm < M) av = A4[gm * 32 + (k0 >> 2) + q];
                As[q * 4 + 0][r] = av.x;
                As[q * 4 + 1][r] = av.y;
                As[q * 4 + 2][r] = av.z;
                As[q * 4 + 3][r] = av.w;
            }
            // load B tile (16 k x 128 n), row-major already
#pragma unroll
            for (int i = 0; i < 2; i++) {
                int idx = tid + i * 256;
                int k = idx >> 5;                  // 0..15
                int f = idx & 31;                  // float4 col
                float4 bv = B4[(k0 + k) * 32 + f];
                *((float4*)&Bs[k][f * 4]) = bv;
            }
            __syncthreads();
#pragma unroll
            for (int k = 0; k < 16; k++) {
                float4 a0 = *((const float4*)&As[k][ty * 8]);
                float4 a1 = *((const float4*)&As[k][ty * 8 + 4]);
                float4 b0 = *((const float4*)&Bs[k][tx * 8]);
                float4 b1 = *((const float4*)&Bs[k][tx * 8 + 4]);
                float a[8] = {a0.x, a0.y, a0.z, a0.w, a1.x, a1.y, a1.z, a1.w};
                float b[8] = {b0.x, b0.y, b0.z, b0.w, b1.x, b1.y, b1.z, b1.w};
#pragma unroll
                for (int i = 0; i < 8; i++)
#pragma unroll
                    for (int j = 0; j < 8; j++)
                        acc[i][j] = fmaf(a[i], b[j], acc[i][j]);
            }
            __syncthreads();
        }
    }

    // epilogue: + bias, leaky relu, store
#pragma unroll
    for (int i = 0; i < 8; i++) {
        int gm = rowBase + ty * 8 + i;
        if (gm >= M) continue;
        float4 o0, o1;
        float* po = (float*)&o0;
#pragma unroll
        for (int j = 0; j < 8; j++) {
            int col = tx * 8 + j;
            float v = acc[i][j] + bias[col];
            v = (v >= 0.f) ? v : SLOPE * v;
            if (j < 4) ((float*)&o0)[j] = v; else ((float*)&o1)[j - 4] = v;
        }
        (void)po;
        float4* Crow = (float4*)&C[gm * NF];
        Crow[tx * 2]     = o0;
        Crow[tx * 2 + 1] = o1;
    }
}

// ---------------- output layer: warp per node, 3 outputs ----------------
__global__ __launch_bounds__(256) void out_kernel(
    const float* __restrict__ agg, const float* __restrict__ h,
    const float* __restrict__ Wl, const float* __restrict__ bl,
    const float* __restrict__ Wr, float* __restrict__ out)
{
    int warp = (blockIdx.x * blockDim.x + threadIdx.x) >> 5;
    int lane = threadIdx.x & 31;
    if (warp >= NN) return;
    float4 a  = ((const float4*)agg)[warp * 32 + lane];
    float4 hv = ((const float4*)h)[warp * 32 + lane];
#pragma unroll
    for (int o = 0; o < 3; o++) {
        float4 wl = ((const float4*)Wl)[o * 32 + lane];
        float4 wr = ((const float4*)Wr)[o * 32 + lane];
        float s = a.x * wl.x + a.y * wl.y + a.z * wl.z + a.w * wl.w
                + hv.x * wr.x + hv.y * wr.y + hv.z * wr.z + hv.w * wr.w;
#pragma unroll
        for (int off = 16; off; off >>= 1)
            s += __shfl_xor_sync(0xffffffff, s, off);
        if (lane == 0) out[warp * 3 + o] = tanhf(s + bl[o]) * 0.5f;
    }
}

// ---------------- host launcher ----------------
extern "C" void kernel_launch(void* const* d_in, const int* in_sizes, int n_in,
                              void* d_out, int out_size)
{
    const float* x      = (const float*)d_in[0];
    const int*   ei     = (const int*)d_in[1];
    const float* Wl     = (const float*)d_in[2];
    const float* bl     = (const float*)d_in[3];
    const float* Wr     = (const float*)d_in[4];
    const float* Wl_out = (const float*)d_in[5];
    const float* bl_out = (const float*)d_in[6];
    const float* Wr_out = (const float*)d_in[7];
    float* out = (float*)d_out;

    const int* src = ei;
    const int* dst = ei + NE;

    void *pH0, *pH1, *pAgg, *pWlT, *pWrT;
    cudaGetSymbolAddress(&pH0, g_h0);
    cudaGetSymbolAddress(&pH1, g_h1);
    cudaGetSymbolAddress(&pAgg, g_agg);
    cudaGetSymbolAddress(&pWlT, g_WlT);
    cudaGetSymbolAddress(&pWrT, g_WrT);
    float* h0  = (float*)pH0;
    float* h1  = (float*)pH1;
    float* agg = (float*)pAgg;
    float* WlT = (float*)pWlT;
    float* WrT = (float*)pWrT;

    // CSR build
    zero_kernel<<<(NN + 255) / 256, 256>>>();
    hist_kernel<<<(NE + 255) / 256, 256>>>(dst);
    scan1_kernel<<<SCAN_B, SCAN_T>>>();
    scan2_kernel<<<1, 1>>>();
    scan3_kernel<<<SCAN_B, SCAN_T>>>();
    fill_kernel<<<(NE + 255) / 256, 256>>>(src, dst);

    // weight transposes
    transpose_kernel<<<(NL * NF * NF + 255) / 256, 256>>>(Wl, Wr);

    const int AGG_BLOCKS  = (NN + 7) / 8;          // warp per node, 8 warps/block
    const int GEMM_BLOCKS = (NN + 127) / 128;

    const float* cur = x;
    for (int i = 0; i < NL; i++) {
        agg_kernel<<<AGG_BLOCKS, 256>>>(cur, agg);
        float* nxt = (i & 1) ? h1 : h0;
        gemm128_kernel<<<GEMM_BLOCKS, 256>>>(agg, cur,
                                             WlT + i * NF * NF, WrT + i * NF * NF,
                                             bl + i * NF, nxt, NN);
        cur = nxt;
    }

    // output conv
    agg_kernel<<<AGG_BLOCKS, 256>>>(cur, agg);
    out_kernel<<<AGG_BLOCKS, 256>>>(agg, cur, Wl_out, bl_out, Wr_out, out);
}

// round 2
// speedup vs baseline: 1.0606x; 1.0606x over previous
#include <cuda_runtime.h>
#include <math.h>
#include <float.h>
#include <stdint.h>

// Problem constants (match reference)
#define NN 100000
#define NE 1600000
#define NF 128
#define NL 7
#define SLOPE 0.02f

// ---------------- device scratch (static, no allocation) ----------------
__device__ int   g_counts[NN];
__device__ int   g_cursor[NN];
__device__ int   g_rowptr[NN + 1];
__device__ int   g_col[NE];
__device__ float g_h0[NN * NF];
__device__ float g_h1[NN * NF];
__device__ float g_agg[NN * NF];
__device__ float g_WlT[NL * NF * NF];   // [l][k][n] = Wl[l][n][k]
__device__ float g_WrT[NL * NF * NF];

// ---------------- init: zero counters + transpose weights ----------------
__global__ void init_kernel(const float* __restrict__ Wl, const float* __restrict__ Wr) {
    int idx = blockIdx.x * blockDim.x + threadIdx.x;
    if (idx < NN) { g_counts[idx] = 0; g_cursor[idx] = 0; }
    if (idx < NL * NF * NF) {
        int l = idx / (NF * NF);
        int r = idx % (NF * NF);
        int k = r / NF;   // input channel
        int n = r % NF;   // output channel
        g_WlT[idx] = Wl[l * NF * NF + n * NF + k];
        g_WrT[idx] = Wr[l * NF * NF + n * NF + k];
    }
}

__global__ void hist_kernel(const int* __restrict__ dst) {
    int e = blockIdx.x * blockDim.x + threadIdx.x;
    if (e < NE) atomicAdd(&g_counts[dst[e]], 1);
}

// single-block exclusive scan over NN counts -> g_rowptr
__global__ void scan_kernel() {
    __shared__ int s[1024];
    __shared__ int carry_s;
    int t = threadIdx.x;
    if (t == 0) carry_s = 0;
    __syncthreads();
    for (int base = 0; base < NN; base += 1024) {
        int c = carry_s;
        int i = base + t;
        int v = (i < NN) ? g_counts[i] : 0;
        s[t] = v;
        __syncthreads();
#pragma unroll
        for (int d = 1; d < 1024; d <<= 1) {
            int add = (t >= d) ? s[t - d] : 0;
            __syncthreads();
            s[t] += add;
            __syncthreads();
        }
        int inc = s[t];
        if (i < NN) g_rowptr[i] = inc - v + c;     // exclusive
        if (t == 1023) carry_s = c + s[1023];
        __syncthreads();
    }
    if (t == 0) g_rowptr[NN] = NE;
}

__global__ void fill_kernel(const int* __restrict__ src, const int* __restrict__ dst) {
    int e = blockIdx.x * blockDim.x + threadIdx.x;
    if (e < NE) {
        int d = dst[e];
        int off = atomicAdd(&g_cursor[d], 1);
        g_col[g_rowptr[d] + off] = src[e];
    }
}

// ---------------- max aggregation: warp per node, float4 per lane ----------------
__device__ __forceinline__ float4 fmax4(float4 a, float4 b) {
    a.x = fmaxf(a.x, b.x); a.y = fmaxf(a.y, b.y);
    a.z = fmaxf(a.z, b.z); a.w = fmaxf(a.w, b.w);
    return a;
}

__global__ __launch_bounds__(256) void agg_kernel(const float* __restrict__ h,
                                                  float* __restrict__ agg) {
    int warp = (blockIdx.x * blockDim.x + threadIdx.x) >> 5;
    int lane = threadIdx.x & 31;
    if (warp >= NN) return;
    int beg = g_rowptr[warp];
    int end = g_rowptr[warp + 1];
    const float4* h4 = (const float4*)h;
    float4 m = make_float4(-FLT_MAX, -FLT_MAX, -FLT_MAX, -FLT_MAX);
    int e = beg;
    for (; e + 4 <= end; e += 4) {
        int s0 = g_col[e], s1 = g_col[e + 1], s2 = g_col[e + 2], s3 = g_col[e + 3];
        float4 v0 = h4[s0 * 32 + lane];
        float4 v1 = h4[s1 * 32 + lane];
        float4 v2 = h4[s2 * 32 + lane];
        float4 v3 = h4[s3 * 32 + lane];
        m = fmax4(m, fmax4(fmax4(v0, v1), fmax4(v2, v3)));
    }
    for (; e < end; e++) {
        int s = g_col[e];
        m = fmax4(m, h4[s * 32 + lane]);
    }
    if (beg == end) m = make_float4(0.f, 0.f, 0.f, 0.f);
    ((float4*)agg)[warp * 32 + lane] = m;
}

// ---------------- 3xTF32 tensor-core dual GEMM + bias + leaky ----------------
// C[M,128] = A0[M,128] @ B0[128,128](k-major) + A1[M,128] @ B1 + bias, then leaky.
// mma.sync.aligned.m16n8k8 tf32 with hi/lo split -> fp32-grade accuracy.

__device__ __forceinline__ void split_tf32(float v, uint32_t& hi, uint32_t& lo) {
    asm("cvt.rna.tf32.f32 %0, %1;" : "=r"(hi) : "f"(v));
    float r = v - __uint_as_float(hi);
    asm("cvt.rna.tf32.f32 %0, %1;" : "=r"(lo) : "f"(r));
}

__device__ __forceinline__ void mma_tf32(float* d, const uint32_t* a, uint32_t b0, uint32_t b1) {
    asm volatile(
        "mma.sync.aligned.m16n8k8.row.col.f32.tf32.tf32.f32 "
        "{%0,%1,%2,%3}, {%4,%5,%6,%7}, {%8,%9}, {%0,%1,%2,%3};"
        : "+f"(d[0]), "+f"(d[1]), "+f"(d[2]), "+f"(d[3])
        : "r"(a[0]), "r"(a[1]), "r"(a[2]), "r"(a[3]), "r"(b0), "r"(b1));
}

#define SA_STRIDE 36    // bank = (4*row + k) % 32 -> conflict-free frag loads
#define SB_STRIDE 136   // bank = (8*k + n) % 32 -> conflict-free frag loads

__global__ __launch_bounds__(256, 2) void gemm128_kernel(
    const float* __restrict__ A0, const float* __restrict__ A1,
    const float* __restrict__ B0, const float* __restrict__ B1,
    const float* __restrict__ bias, float* __restrict__ C, int M)
{
    __shared__ float sA[128 * SA_STRIDE];
    __shared__ float sB[32 * SB_STRIDE];

    int tid = threadIdx.x;
    int lane = tid & 31;
    int warp = tid >> 5;
    int wm = warp & 3;       // 4 warp rows of 32
    int wn = warp >> 2;      // 2 warp cols of 64
    int rowBase = blockIdx.x * 128;

    float acc[2][8][4];
#pragma unroll
    for (int mt = 0; mt < 2; mt++)
#pragma unroll
        for (int nt = 0; nt < 8; nt++)
#pragma unroll
            for (int q = 0; q < 4; q++) acc[mt][nt][q] = 0.f;

#pragma unroll
    for (int half = 0; half < 2; half++) {
        const float4* A4 = (const float4*)(half ? A1 : A0);
        const float4* B4 = (const float4*)(half ? B1 : B0);
#pragma unroll
        for (int chunk = 0; chunk < 4; chunk++) {
            int k0 = chunk * 32;
            __syncthreads();
            // stage A tile: 128 rows x 32 k (fp32, padded stride)
#pragma unroll
            for (int i = 0; i < 4; i++) {
                int idx = tid + i * 256;         // 0..1023 float4s
                int r = idx >> 3;                // 0..127
                int q = idx & 7;                 // float4 within 32-k chunk
                int gm = rowBase + r;
                float4 av = make_float4(0.f, 0.f, 0.f, 0.f);
                if (gm < M) av = A4[gm * 32 + (k0 >> 2) + q];
                float* p = &sA[r * SA_STRIDE + q * 4];
                p[0] = av.x; p[1] = av.y; p[2] = av.z; p[3] = av.w;
            }
            // stage B tile: 32 k x 128 n
#pragma unroll
            for (int i = 0; i < 4; i++) {
                int idx = tid + i * 256;
                int k = idx >> 5;                // 0..31
                int f = idx & 31;                // float4 col
                float4 bv = B4[(k0 + k) * 32 + f];
                float* p = &sB[k * SB_STRIDE + f * 4];
                p[0] = bv.x; p[1] = bv.y; p[2] = bv.z; p[3] = bv.w;
            }
            __syncthreads();

#pragma unroll
            for (int k8 = 0; k8 < 4; k8++) {
                int kk = k8 * 8 + (lane & 3);
                uint32_t ahi[2][4], alo[2][4];
#pragma unroll
                for (int mt = 0; mt < 2; mt++) {
                    int r = wm * 32 + mt * 16 + (lane >> 2);
                    float a0 = sA[r * SA_STRIDE + kk];
                    float a1 = sA[(r + 8) * SA_STRIDE + kk];
                    float a2 = sA[r * SA_STRIDE + kk + 4];
                    float a3 = sA[(r + 8) * SA_STRIDE + kk + 4];
                    split_tf32(a0, ahi[mt][0], alo[mt][0]);
                    split_tf32(a1, ahi[mt][1], alo[mt][1]);
                    split_tf32(a2, ahi[mt][2], alo[mt][2]);
                    split_tf32(a3, ahi[mt][3], alo[mt][3]);
                }
#pragma unroll
                for (int nt = 0; nt < 8; nt++) {
                    int n = wn * 64 + nt * 8 + (lane >> 2);
                    float b0f = sB[kk * SB_STRIDE + n];
                    float b1f = sB[(kk + 4) * SB_STRIDE + n];
                    uint32_t bh0, bl0, bh1, bl1;
                    split_tf32(b0f, bh0, bl0);
                    split_tf32(b1f, bh1, bl1);
#pragma unroll
                    for (int mt = 0; mt < 2; mt++) {
                        mma_tf32(acc[mt][nt], alo[mt], bh0, bh1);
                        mma_tf32(acc[mt][nt], ahi[mt], bl0, bl1);
                        mma_tf32(acc[mt][nt], ahi[mt], bh0, bh1);
                    }
                }
            }
        }
    }

    // epilogue: + bias, leaky relu, store (d-frag: c0,c1 row g, c2,c3 row g+8)
#pragma unroll
    for (int mt = 0; mt < 2; mt++) {
        int r0 = rowBase + wm * 32 + mt * 16 + (lane >> 2);
#pragma unroll
        for (int nt = 0; nt < 8; nt++) {
            int col = wn * 64 + nt * 8 + 2 * (lane & 3);
            float bv0 = bias[col], bv1 = bias[col + 1];
            float v0 = acc[mt][nt][0] + bv0;
            float v1 = acc[mt][nt][1] + bv1;
            float v2 = acc[mt][nt][2] + bv0;
            float v3 = acc[mt][nt][3] + bv1;
            v0 = (v0 >= 0.f) ? v0 : SLOPE * v0;
            v1 = (v1 >= 0.f) ? v1 : SLOPE * v1;
            v2 = (v2 >= 0.f) ? v2 : SLOPE * v2;
            v3 = (v3 >= 0.f) ? v3 : SLOPE * v3;
            if (r0 < M)     *((float2*)&C[r0 * NF + col])       = make_float2(v0, v1);
            if (r0 + 8 < M) *((float2*)&C[(r0 + 8) * NF + col]) = make_float2(v2, v3);
        }
    }
}

// ---------------- output layer: warp per node, 3 outputs ----------------
__global__ __launch_bounds__(256) void out_kernel(
    const float* __restrict__ agg, const float* __restrict__ h,
    const float* __restrict__ Wl, const float* __restrict__ bl,
    const float* __restrict__ Wr, float* __restrict__ out)
{
    int warp = (blockIdx.x * blockDim.x + threadIdx.x) >> 5;
    int lane = threadIdx.x & 31;
    if (warp >= NN) return;
    float4 a  = ((const float4*)agg)[warp * 32 + lane];
    float4 hv = ((const float4*)h)[warp * 32 + lane];
#pragma unroll
    for (int o = 0; o < 3; o++) {
        float4 wl = ((const float4*)Wl)[o * 32 + lane];
        float4 wr = ((const float4*)Wr)[o * 32 + lane];
        float s = a.x * wl.x + a.y * wl.y + a.z * wl.z + a.w * wl.w
                + hv.x * wr.x + hv.y * wr.y + hv.z * wr.z + hv.w * wr.w;
#pragma unroll
        for (int off = 16; off; off >>= 1)
            s += __shfl_xor_sync(0xffffffff, s, off);
        if (lane == 0) out[warp * 3 + o] = tanhf(s + bl[o]) * 0.5f;
    }
}

// ---------------- host launcher ----------------
extern "C" void kernel_launch(void* const* d_in, const int* in_sizes, int n_in,
                              void* d_out, int out_size)
{
    const float* x      = (const float*)d_in[0];
    const int*   ei     = (const int*)d_in[1];
    const float* Wl     = (const float*)d_in[2];
    const float* bl     = (const float*)d_in[3];
    const float* Wr     = (const float*)d_in[4];
    const float* Wl_out = (const float*)d_in[5];
    const float* bl_out = (const float*)d_in[6];
    const float* Wr_out = (const float*)d_in[7];
    float* out = (float*)d_out;

    const int* src = ei;
    const int* dst = ei + NE;

    void *pH0, *pH1, *pAgg, *pWlT, *pWrT;
    cudaGetSymbolAddress(&pH0, g_h0);
    cudaGetSymbolAddress(&pH1, g_h1);
    cudaGetSymbolAddress(&pAgg, g_agg);
    cudaGetSymbolAddress(&pWlT, g_WlT);
    cudaGetSymbolAddress(&pWrT, g_WrT);
    float* h0  = (float*)pH0;
    float* h1  = (float*)pH1;
    float* agg = (float*)pAgg;
    float* WlT = (float*)pWlT;
    float* WrT = (float*)pWrT;

    // CSR build + weight transpose (4 launches, so launch #6 = first GEMM for ncu)
    const int INIT_N = NL * NF * NF;  // 114688 > NN
    init_kernel<<<(INIT_N + 255) / 256, 256>>>(Wl, Wr);
    hist_kernel<<<(NE + 255) / 256, 256>>>(dst);
    scan_kernel<<<1, 1024>>>();
    fill_kernel<<<(NE + 255) / 256, 256>>>(src, dst);

    const int AGG_BLOCKS  = (NN + 7) / 8;          // warp per node, 8 warps/block
    const int GEMM_BLOCKS = (NN + 127) / 128;

    const float* cur = x;
    for (int i = 0; i < NL; i++) {
        agg_kernel<<<AGG_BLOCKS, 256>>>(cur, agg);
        float* nxt = (i & 1) ? h1 : h0;
        gemm128_kernel<<<GEMM_BLOCKS, 256>>>(agg, cur,
                                             WlT + i * NF * NF, WrT + i * NF * NF,
                                             bl + i * NF, nxt, NN);
        cur = nxt;
    }

    // output conv
    agg_kernel<<<AGG_BLOCKS, 256>>>(cur, agg);
    out_kernel<<<AGG_BLOCKS, 256>>>(agg, cur, Wl_out, bl_out, Wr_out, out);
}

// round 4
// speedup vs baseline: 1.1270x; 1.0626x over previous
#include <cuda_runtime.h>
#include <cuda_bf16.h>
#include <math.h>
#include <float.h>
#include <stdint.h>

// Problem constants (match reference)
#define NN 100000
#define NE 1600000
#define NF 128
#define NL 7
#define SLOPE 0.02f

// ---------------- device scratch (static, no allocation) ----------------
__device__ int   g_counts[NN];
__device__ int   g_cursor[NN];
__device__ int   g_rowptr[NN + 1];
__device__ int   g_col[NE];
__device__ float g_h0[NN * NF];
__device__ float g_h1[NN * NF];
__device__ float g_agg[NN * NF];
// pre-split weights: hi/lo bf16, layout [l][n][k] (same as input W)
__device__ __align__(16) uint16_t g_WlHi[NL * NF * NF];
__device__ __align__(16) uint16_t g_WlLo[NL * NF * NF];
__device__ __align__(16) uint16_t g_WrHi[NL * NF * NF];
__device__ __align__(16) uint16_t g_WrLo[NL * NF * NF];

// ---------------- init: zero counters + pre-split weights ----------------
__global__ void init_kernel(const float* __restrict__ Wl, const float* __restrict__ Wr) {
    int idx = blockIdx.x * blockDim.x + threadIdx.x;
    if (idx < NN) { g_counts[idx] = 0; g_cursor[idx] = 0; }
    if (idx < NL * NF * NF) {
        float a = Wl[idx];
        __nv_bfloat16 h = __float2bfloat16(a);
        g_WlHi[idx] = __bfloat16_as_ushort(h);
        g_WlLo[idx] = __bfloat16_as_ushort(__float2bfloat16(a - __bfloat162float(h)));
        float b = Wr[idx];
        __nv_bfloat16 hb = __float2bfloat16(b);
        g_WrHi[idx] = __bfloat16_as_ushort(hb);
        g_WrLo[idx] = __bfloat16_as_ushort(__float2bfloat16(b - __bfloat162float(hb)));
    }
}

__global__ void hist_kernel(const int* __restrict__ dst) {
    int e = blockIdx.x * blockDim.x + threadIdx.x;
    if (e < NE) atomicAdd(&g_counts[dst[e]], 1);
}

// single-block exclusive scan over NN counts -> g_rowptr
__global__ void scan_kernel() {
    __shared__ int s[1024];
    __shared__ int carry_s;
    int t = threadIdx.x;
    if (t == 0) carry_s = 0;
    __syncthreads();
    for (int base = 0; base < NN; base += 1024) {
        int c = carry_s;
        int i = base + t;
        int v = (i < NN) ? g_counts[i] : 0;
        s[t] = v;
        __syncthreads();
#pragma unroll
        for (int d = 1; d < 1024; d <<= 1) {
            int add = (t >= d) ? s[t - d] : 0;
            __syncthreads();
            s[t] += add;
            __syncthreads();
        }
        int inc = s[t];
        if (i < NN) g_rowptr[i] = inc - v + c;     // exclusive
        if (t == 1023) carry_s = c + s[1023];
        __syncthreads();
    }
    if (t == 0) g_rowptr[NN] = NE;
}

__global__ void fill_kernel(const int* __restrict__ src, const int* __restrict__ dst) {
    int e = blockIdx.x * blockDim.x + threadIdx.x;
    if (e < NE) {
        int d = dst[e];
        int off = atomicAdd(&g_cursor[d], 1);
        g_col[g_rowptr[d] + off] = src[e];
    }
}

// ---------------- helpers ----------------
__device__ __forceinline__ float4 fmax4(float4 a, float4 b) {
    a.x = fmaxf(a.x, b.x); a.y = fmaxf(a.y, b.y);
    a.z = fmaxf(a.z, b.z); a.w = fmaxf(a.w, b.w);
    return a;
}

__device__ __forceinline__ uint32_t smem_u32(const void* p) {
    uint32_t a;
    asm("{ .reg .u64 t; cvta.to.shared.u64 t, %1; cvt.u32.u64 %0, t; }" : "=r"(a) : "l"(p));
    return a;
}

__device__ __forceinline__ void ldm4(uint32_t* r, uint32_t addr) {
    asm volatile("ldmatrix.sync.aligned.m8n8.x4.shared.b16 {%0,%1,%2,%3}, [%4];"
                 : "=r"(r[0]), "=r"(r[1]), "=r"(r[2]), "=r"(r[3]) : "r"(addr));
}

__device__ __forceinline__ void mma_bf16(float* d, const uint32_t* a, uint32_t b0, uint32_t b1) {
    asm volatile(
        "mma.sync.aligned.m16n8k16.row.col.f32.bf16.bf16.f32 "
        "{%0,%1,%2,%3}, {%4,%5,%6,%7}, {%8,%9}, {%0,%1,%2,%3};"
        : "+f"(d[0]), "+f"(d[1]), "+f"(d[2]), "+f"(d[3])
        : "r"(a[0]), "r"(a[1]), "r"(a[2]), "r"(a[3]), "r"(b0), "r"(b1));
}

// ---------------- standalone max aggregation (final layer only) ----------------
__global__ __launch_bounds__(256) void agg_kernel(const float* __restrict__ h,
                                                  float* __restrict__ agg) {
    int warp = (blockIdx.x * blockDim.x + threadIdx.x) >> 5;
    int lane = threadIdx.x & 31;
    if (warp >= NN) return;
    int beg = g_rowptr[warp];
    int end = g_rowptr[warp + 1];
    const float4* h4 = (const float4*)h;
    float4 m = make_float4(-FLT_MAX, -FLT_MAX, -FLT_MAX, -FLT_MAX);
    int e = beg;
    for (; e + 4 <= end; e += 4) {
        int s0 = g_col[e], s1 = g_col[e + 1], s2 = g_col[e + 2], s3 = g_col[e + 3];
        float4 v0 = h4[s0 * 32 + lane];
        float4 v1 = h4[s1 * 32 + lane];
        float4 v2 = h4[s2 * 32 + lane];
        float4 v3 = h4[s3 * 32 + lane];
        m = fmax4(m, fmax4(fmax4(v0, v1), fmax4(v2, v3)));
    }
    for (; e < end; e++) {
        int s = g_col[e];
        m = fmax4(m, h4[s * 32 + lane]);
    }
    if (beg == end) m = make_float4(0.f, 0.f, 0.f, 0.f);
    ((float4*)agg)[warp * 32 + lane] = m;
}

// ================= fused agg + bf16x3 tensor-core dual GEMM =================
// Per CTA: 128 rows. Computes agg in-kernel (CSR gather), stages hi/lo bf16 tiles,
// runs C = agg@Wl^T + h@Wr^T via mma.sync bf16 (3-pass split), bias + leaky.
//
// smem: A tile 128 rows x 128 k bf16, stride 272B (conflict-free ldmatrix).
//       B tile 64 n-rows x 128 k bf16, stride 272B (two n-chunks).
#define A_STRIDE 272
#define SA_HI 0
#define SA_LO 34816
#define SB_HI 69632
#define SB_LO 87040
#define SM_TOT 104448

// split v into hi/lo bf16 and write 4 elements (8B each tile) at (row, q)
__device__ __forceinline__ void write_split(char* smem, int row, int q, float4 v) {
    __nv_bfloat16 hx = __float2bfloat16(v.x);
    __nv_bfloat16 hy = __float2bfloat16(v.y);
    __nv_bfloat16 hz = __float2bfloat16(v.z);
    __nv_bfloat16 hw = __float2bfloat16(v.w);
    uint32_t hi01 = ((uint32_t)__bfloat16_as_ushort(hy) << 16) | __bfloat16_as_ushort(hx);
    uint32_t hi23 = ((uint32_t)__bfloat16_as_ushort(hw) << 16) | __bfloat16_as_ushort(hz);
    __nv_bfloat16 lx = __float2bfloat16(v.x - __bfloat162float(hx));
    __nv_bfloat16 ly = __float2bfloat16(v.y - __bfloat162float(hy));
    __nv_bfloat16 lz = __float2bfloat16(v.z - __bfloat162float(hz));
    __nv_bfloat16 lw = __float2bfloat16(v.w - __bfloat162float(hw));
    uint32_t lo01 = ((uint32_t)__bfloat16_as_ushort(ly) << 16) | __bfloat16_as_ushort(lx);
    uint32_t lo23 = ((uint32_t)__bfloat16_as_ushort(lw) << 16) | __bfloat16_as_ushort(lz);
    uint32_t off = (uint32_t)(row * A_STRIDE + q * 8);
    *(uint2*)(smem + SA_HI + off) = make_uint2(hi01, hi23);
    *(uint2*)(smem + SA_LO + off) = make_uint2(lo01, lo23);
}

// stage one 64-n chunk of pre-split weights into sB
__device__ __forceinline__ void stage_w(char* smem, const uint16_t* __restrict__ WHi,
                                        const uint16_t* __restrict__ WLo, int nbase, int tid) {
#pragma unroll
    for (int i = 0; i < 4; i++) {
        int idx = tid + i * 256;         // 0..1023
        int nl = idx >> 4;               // 0..63
        int q  = idx & 15;               // uint4 within 128-k row
        const uint4* sh = (const uint4*)(WHi + (size_t)(nbase + nl) * NF);
        const uint4* sl = (const uint4*)(WLo + (size_t)(nbase + nl) * NF);
        *(uint4*)(smem + SB_HI + nl * A_STRIDE + q * 16) = sh[q];
        *(uint4*)(smem + SB_LO + nl * A_STRIDE + q * 16) = sl[q];
    }
}

// stage 128 h-rows (fp32 gmem -> split bf16 smem)
__device__ __forceinline__ void stage_h(char* smem, const float* __restrict__ h,
                                        int rowBase, int M, int tid) {
    const float4* h4 = (const float4*)h;
#pragma unroll
    for (int i = 0; i < 16; i++) {
        int idx = tid + i * 256;
        int row = idx >> 5;
        int q   = idx & 31;
        int gm  = rowBase + row;
        float4 v = make_float4(0.f, 0.f, 0.f, 0.f);
        if (gm < M) v = h4[gm * 32 + q];
        write_split(smem, row, q, v);
    }
}

// gather (max-agg) 16 rows per warp, split into sA
__device__ __forceinline__ void stage_gather(char* smem, const float* __restrict__ h,
                                             int rowBase, int M, int wid, int lane) {
    const float4* h4 = (const float4*)h;
#pragma unroll 1
    for (int j = 0; j < 16; j++) {
        int r = wid * 16 + j;
        int gm = rowBase + r;
        float4 m = make_float4(0.f, 0.f, 0.f, 0.f);
        if (gm < M) {
            int beg = g_rowptr[gm];
            int end = g_rowptr[gm + 1];
            if (beg < end) {
                float4 a = make_float4(-FLT_MAX, -FLT_MAX, -FLT_MAX, -FLT_MAX);
                int e = beg;
                for (; e + 4 <= end; e += 4) {
                    int s0 = g_col[e], s1 = g_col[e + 1], s2 = g_col[e + 2], s3 = g_col[e + 3];
                    float4 v0 = h4[s0 * 32 + lane];
                    float4 v1 = h4[s1 * 32 + lane];
                    float4 v2 = h4[s2 * 32 + lane];
                    float4 v3 = h4[s3 * 32 + lane];
                    a = fmax4(a, fmax4(fmax4(v0, v1), fmax4(v2, v3)));
                }
                for (; e < end; e++) a = fmax4(a, h4[g_col[e] * 32 + lane]);
                m = a;
            }
        }
        write_split(smem, r, lane, m);
    }
}

// one K=128 sweep for one 64-n chunk: 3-pass bf16 split
__device__ __forceinline__ void mma_block(float acc[8][4],
                                          uint32_t aHiB, uint32_t aLoB,
                                          uint32_t bHiB, uint32_t bLoB) {
#pragma unroll
    for (int ks = 0; ks < 8; ks++) {
        uint32_t ko = ks * 32;   // 16 bf16 = 32 bytes per k-step
        uint32_t ah[4], al[4];
        ldm4(ah, aHiB + ko);
        ldm4(al, aLoB + ko);
#pragma unroll
        for (int p = 0; p < 4; p++) {
            uint32_t bh[4], blx[4];
            uint32_t po = (uint32_t)(p * 16 * A_STRIDE) + ko;
            ldm4(bh,  bHiB + po);
            ldm4(blx, bLoB + po);
            mma_bf16(acc[2 * p],     ah, bh[0],  bh[1]);
            mma_bf16(acc[2 * p],     ah, blx[0], blx[1]);
            mma_bf16(acc[2 * p],     al, bh[0],  bh[1]);
            mma_bf16(acc[2 * p + 1], ah, bh[2],  bh[3]);
            mma_bf16(acc[2 * p + 1], ah, blx[2], blx[3]);
            mma_bf16(acc[2 * p + 1], al, bh[2],  bh[3]);
        }
    }
}

__global__ __launch_bounds__(256, 2) void gemm_fused_kernel(
    const float* __restrict__ h,
    const uint16_t* __restrict__ WlHi, const uint16_t* __restrict__ WlLo,
    const uint16_t* __restrict__ WrHi, const uint16_t* __restrict__ WrLo,
    const float* __restrict__ bias, float* __restrict__ C, int M)
{
    extern __shared__ char smem[];
    uint32_t su = smem_u32(smem);
    int tid = threadIdx.x;
    int lane = tid & 31;
    int wid = tid >> 5;
    int rowBase = blockIdx.x * 128;

    // per-lane ldmatrix base addresses
    int lr = lane & 7, g = lane >> 3;
    uint32_t aOff = (uint32_t)((wid * 16 + lr + (g & 1) * 8) * A_STRIDE + (g >> 1) * 16);
    uint32_t bOff = (uint32_t)((lr + (g >> 1) * 8) * A_STRIDE + (g & 1) * 16);
    uint32_t aHiB = su + SA_HI + aOff, aLoB = su + SA_LO + aOff;
    uint32_t bHiB = su + SB_HI + bOff, bLoB = su + SB_LO + bOff;

    float acc0[8][4], acc1[8][4];
#pragma unroll
    for (int i = 0; i < 8; i++)
#pragma unroll
        for (int q = 0; q < 4; q++) { acc0[i][q] = 0.f; acc1[i][q] = 0.f; }

    // ---- half 0: A = agg(h), B = Wl ----
    stage_gather(smem, h, rowBase, M, wid, lane);
    stage_w(smem, WlHi, WlLo, 0, tid);
    __syncthreads();
    mma_block(acc0, aHiB, aLoB, bHiB, bLoB);
    __syncthreads();
    stage_w(smem, WlHi, WlLo, 64, tid);
    __syncthreads();
    mma_block(acc1, aHiB, aLoB, bHiB, bLoB);
    __syncthreads();

    // ---- half 1: A = h rows, B = Wr ----
    stage_h(smem, h, rowBase, M, tid);
    stage_w(smem, WrHi, WrLo, 0, tid);
    __syncthreads();
    mma_block(acc0, aHiB, aLoB, bHiB, bLoB);
    __syncthreads();
    stage_w(smem, WrHi, WrLo, 64, tid);
    __syncthreads();
    mma_block(acc1, aHiB, aLoB, bHiB, bLoB);

    // ---- epilogue: bias + leaky, direct stores ----
    int r0 = rowBase + wid * 16 + (lane >> 2);
#pragma unroll
    for (int half = 0; half < 2; half++) {
        float (*A)[4] = half ? acc1 : acc0;
        int cbase = half * 64;
#pragma unroll
        for (int nt = 0; nt < 8; nt++) {
            int col = cbase + nt * 8 + 2 * (lane & 3);
            float b0 = bias[col], b1 = bias[col + 1];
            float v0 = A[nt][0] + b0;
            float v1 = A[nt][1] + b1;
            float v2 = A[nt][2] + b0;
            float v3 = A[nt][3] + b1;
            v0 = (v0 >= 0.f) ? v0 : SLOPE * v0;
            v1 = (v1 >= 0.f) ? v1 : SLOPE * v1;
            v2 = (v2 >= 0.f) ? v2 : SLOPE * v2;
            v3 = (v3 >= 0.f) ? v3 : SLOPE * v3;
            if (r0 < M)     *((float2*)&C[(size_t)r0 * NF + col])       = make_float2(v0, v1);
            if (r0 + 8 < M) *((float2*)&C[(size_t)(r0 + 8) * NF + col]) = make_float2(v2, v3);
        }
    }
}

// ---------------- output layer: warp per node, 3 outputs ----------------
__global__ __launch_bounds__(256) void out_kernel(
    const float* __restrict__ agg, const float* __restrict__ h,
    const float* __restrict__ Wl, const float* __restrict__ bl,
    const float* __restrict__ Wr, float* __restrict__ out)
{
    int warp = (blockIdx.x * blockDim.x + threadIdx.x) >> 5;
    int lane = threadIdx.x & 31;
    if (warp >= NN) return;
    float4 a  = ((const float4*)agg)[warp * 32 + lane];
    float4 hv = ((const float4*)h)[warp * 32 + lane];
#pragma unroll
    for (int o = 0; o < 3; o++) {
        float4 wl = ((const float4*)Wl)[o * 32 + lane];
        float4 wr = ((const float4*)Wr)[o * 32 + lane];
        float s = a.x * wl.x + a.y * wl.y + a.z * wl.z + a.w * wl.w
                + hv.x * wr.x + hv.y * wr.y + hv.z * wr.z + hv.w * wr.w;
#pragma unroll
        for (int off = 16; off; off >>= 1)
            s += __shfl_xor_sync(0xffffffff, s, off);
        if (lane == 0) out[warp * 3 + o] = tanhf(s + bl[o]) * 0.5f;
    }
}

// ---------------- host launcher ----------------
extern "C" void kernel_launch(void* const* d_in, const int* in_sizes, int n_in,
                              void* d_out, int out_size)
{
    const float* x      = (const float*)d_in[0];
    const int*   ei     = (const int*)d_in[1];
    const float* Wl     = (const float*)d_in[2];
    const float* bl     = (const float*)d_in[3];
    const float* Wr     = (const float*)d_in[4];
    const float* Wl_out = (const float*)d_in[5];
    const float* bl_out = (const float*)d_in[6];
    const float* Wr_out = (const float*)d_in[7];
    float* out = (float*)d_out;

    const int* src = ei;
    const int* dst = ei + NE;

    void *pH0, *pH1, *pAgg, *pWlHi, *pWlLo, *pWrHi, *pWrLo;
    cudaGetSymbolAddress(&pH0, g_h0);
    cudaGetSymbolAddress(&pH1, g_h1);
    cudaGetSymbolAddress(&pAgg, g_agg);
    cudaGetSymbolAddress(&pWlHi, g_WlHi);
    cudaGetSymbolAddress(&pWlLo, g_WlLo);
    cudaGetSymbolAddress(&pWrHi, g_WrHi);
    cudaGetSymbolAddress(&pWrLo, g_WrLo);
    float* h0  = (float*)pH0;
    float* h1  = (float*)pH1;
    float* agg = (float*)pAgg;
    uint16_t* wlHi = (uint16_t*)pWlHi;
    uint16_t* wlLo = (uint16_t*)pWlLo;
    uint16_t* wrHi = (uint16_t*)pWrHi;
    uint16_t* wrLo = (uint16_t*)pWrLo;

    cudaFuncSetAttribute(gemm_fused_kernel, cudaFuncAttributeMaxDynamicSharedMemorySize, SM_TOT);

    // CSR build + weight pre-split
    const int INIT_N = NL * NF * NF;  // 114688 > NN
    init_kernel<<<(INIT_N + 255) / 256, 256>>>(Wl, Wr);
    hist_kernel<<<(NE + 255) / 256, 256>>>(dst);
    scan_kernel<<<1, 1024>>>();
    fill_kernel<<<(NE + 255) / 256, 256>>>(src, dst);

    const int AGG_BLOCKS  = (NN + 7) / 8;
    const int GEMM_BLOCKS = (NN + 127) / 128;

    const float* cur = x;
    for (int i = 0; i < NL; i++) {
        float* nxt = (i & 1) ? h1 : h0;
        gemm_fused_kernel<<<GEMM_BLOCKS, 256, SM_TOT>>>(
            cur,
            wlHi + (size_t)i * NF * NF, wlLo + (size_t)i * NF * NF,
            wrHi + (size_t)i * NF * NF, wrLo + (size_t)i * NF * NF,
            bl + i * NF, nxt, NN);
        cur = nxt;
    }

    // output conv
    agg_kernel<<<AGG_BLOCKS, 256>>>(cur, agg);
    out_kernel<<<AGG_BLOCKS, 256>>>(agg, cur, Wl_out, bl_out, Wr_out, out);
}